// round 17
// baseline (speedup 1.0000x reference)
#include <cuda_runtime.h>
#include <cstdint>

// Problem constants
#define BATCH 64
#define TSTEPS 2048
#define DIN 128
#define HID 256
#define DOUT 128
#define G4H (4*HID)        // 1024

// Scan tiling: 16 column-groups x 8 batch-groups = 128 CTAs (bids 0-127)
#define NCTA_SCAN 128
#define JPC 16             // hidden units per CTA
#define NCOL 64            // gate columns per CTA
#define BPC 8              // batches per CTA
#define KC 32              // K per warp (8 warps)
#define NTHREADS 256

// xproj: 20 persistent CTAs (bids 128-147) loop over 1024 tiles
#define NCTA_XP 20
#define NCTA_TOTAL (NCTA_SCAN + NCTA_XP)
#define NTILES (128 * 8)   // (tblk, bg)

// scan SMEM (floats)
#define SWSTR 66                         // sW2 [k][c] staging stride
#define PSTR 70                          // sPart row stride
#define SM_SW2   0                       // 256*66 = 16896 (setup only)
#define SM_H     (SM_SW2 + 256*SWSTR)    // sH [k(256)][b(8)] = 2048
#define SM_PART  (SM_H + 256*8)          // 2 x 8 x 8 x PSTR = 8960
#define SM_C     (SM_PART + 2*8*8*PSTR)  // 128
#define SM_FLOATS (SM_C + 128)

// xproj SMEM (floats)
#define XP_XSTRIDE 133
#define XP_WSTRIDE 132
#define XPK_SX    0
#define XPK_SW    (128*XP_XSTRIDE)
#define XPK_FLOATS (XPK_SW + 128*XP_WSTRIDE)
#define XPK_BYTES (XPK_FLOATS*4)         // ~136 KB = fused kernel request

// Global scratch
__device__ __align__(16) float g_xp[(size_t)TSTEPS * 16 * 8 * 512];      // [t][cg][bg][bb*64+c]
// tagged h words: {hi32 = step tag, lo32 = h bits}; [buf][bg][cg][lj*8+bb]
__device__ __align__(16) unsigned long long g_hx[2][8][16][JPC*BPC];
__device__ unsigned xp_cnt[128 * 32];                                    // per tblk, 128B apart

__device__ __forceinline__ uint32_t smem_u32(const void* p) {
    return (uint32_t)__cvta_generic_to_shared(p);
}
__device__ __forceinline__ unsigned long long ld_relaxed_u64(
        const unsigned long long* p) {
    unsigned long long v;
    asm volatile("ld.relaxed.gpu.global.u64 %0, [%1];"
                 : "=l"(v) : "l"(p) : "memory");
    return v;
}

// stage one 16-byte packet (4 tagged words' low 32 bits) into sH
#define STAGE_BLOCK(vx, OFF)                                              \
    asm volatile("st.shared.v4.f32 [%0], {%1,%2,%3,%4};"                  \
                 :: "r"(hstore + (OFF)),                                  \
                    "f"(__uint_as_float((unsigned)(vx)[0])),              \
                    "f"(__uint_as_float((unsigned)(vx)[1])),              \
                    "f"(__uint_as_float((unsigned)(vx)[2])),              \
                    "f"(__uint_as_float((unsigned)(vx)[3])))

// half GEMM over k = KOFF .. KOFF+15 (accumulates into acc)
#define GEMM_HALF(KOFF)                                                   \
    do {                                                                  \
        _Pragma("unroll")                                                 \
        for (int k = 0; k < 16; k++) {                                    \
            float h0, h1, h2f, h3;                                        \
            asm volatile("ld.shared.v4.f32 {%0,%1,%2,%3}, [%4];"          \
                         : "=f"(h0), "=f"(h1), "=f"(h2f), "=f"(h3)        \
                         : "r"(hbase + ((KOFF) + k) * 32));               \
            unsigned long long hh[4];                                     \
            asm("mov.b64 %0, {%1, %1};" : "=l"(hh[0]) : "f"(h0));         \
            asm("mov.b64 %0, {%1, %1};" : "=l"(hh[1]) : "f"(h1));         \
            asm("mov.b64 %0, {%1, %1};" : "=l"(hh[2]) : "f"(h2f));        \
            asm("mov.b64 %0, {%1, %1};" : "=l"(hh[3]) : "f"(h3));         \
            _Pragma("unroll")                                             \
            for (int i = 0; i < 4; i++) {                                 \
                asm volatile("fma.rn.f32x2 %0, %1, %2, %0;"               \
                    : "+l"(acc[0][i]) : "l"(hh[i]), "l"(wreg[0][(KOFF)+k])); \
                asm volatile("fma.rn.f32x2 %0, %1, %2, %0;"               \
                    : "+l"(acc[1][i]) : "l"(hh[i]), "l"(wreg[1][(KOFF)+k])); \
            }                                                             \
        }                                                                 \
    } while (0)

// poll remaining stale words of one block until all tags match
#define POLL_BLOCK(vx, px)                                                \
    do {                                                                  \
        for (;;) {                                                        \
            bool ok_ = true;                                              \
            _Pragma("unroll")                                             \
            for (int i = 0; i < 4; i++) {                                 \
                if ((unsigned)((vx)[i] >> 32) != exp_tag) {               \
                    (vx)[i] = ld_relaxed_u64((px) + i); ok_ = false;      \
                }                                                         \
            }                                                             \
            if (__all_sync(0xffffffffu, ok_)) break;                      \
        }                                                                 \
    } while (0)

// ---------------------------------------------------------------------------
__global__ void init_kernel() {
    int i = blockIdx.x * blockDim.x + threadIdx.x;
    int total = 2 * 8 * 16 * JPC * BPC;
    if (i < total) ((unsigned long long*)g_hx)[i] = 0ull;  // tag 0, h = 0
    if (i < 128 * 32) xp_cnt[i] = 0u;
}

// ===========================================================================
// xproj tile body (persistent CTA calls this per tile)
// g_xp[t][cg][bg][bb*64 + gate*16+lj] = x[b,t,:] . W_x[:, gcol] + bias
// ===========================================================================
__device__ void xproj_tile(const float* __restrict__ x,
                           const float* __restrict__ W_x,
                           const float* __restrict__ bias,
                           int idx) {
    extern __shared__ float smem[];
    float* sX = smem + XPK_SX;
    float* sW = smem + XPK_SW;

    const int tid  = threadIdx.x;
    const int tblk = idx >> 3;
    const int bg   = idx & 7;

    __syncthreads();   // protect sX reuse across tile iterations

    for (int i = tid; i < 128 * 32; i += NTHREADS) {
        int r = i >> 5, f4 = i & 31;
        int tt = r >> 3, bb = r & 7;
        int b = bg * 8 + bb, t = tblk * 16 + tt;
        float4 v = __ldg(reinterpret_cast<const float4*>(
            x + ((size_t)b * TSTEPS + t) * DIN) + f4);
        float* dst = sX + r * XP_XSTRIDE + f4 * 4;
        dst[0] = v.x; dst[1] = v.y; dst[2] = v.z; dst[3] = v.w;
    }

    const int cq = tid & 7;
    const int rg = tid >> 3;

    for (int p = 0; p < 8; p++) {
        const int cp0 = p * 128;
        __syncthreads();
        for (int i = tid; i < 128 * 32; i += NTHREADS) {
            int d = i >> 5, c4 = i & 31;
            float4 v = __ldg(reinterpret_cast<const float4*>(
                W_x + (size_t)d * G4H + cp0) + c4);
            float* dst = sW + d * XP_WSTRIDE + c4 * 4;
            dst[0] = v.x; dst[1] = v.y; dst[2] = v.z; dst[3] = v.w;
        }
        __syncthreads();

        unsigned long long acc[4][8];
        #pragma unroll
        for (int qq = 0; qq < 8; qq++) {
            float2 bv = __ldg(reinterpret_cast<const float2*>(
                bias + cp0 + 2 * (cq + 8 * qq)));
            unsigned long long bu;
            asm("mov.b64 %0, {%1, %2};" : "=l"(bu) : "f"(bv.x), "f"(bv.y));
            #pragma unroll
            for (int rr = 0; rr < 4; rr++) acc[rr][qq] = bu;
        }

        #pragma unroll 4
        for (int d = 0; d < 128; d++) {
            unsigned long long x2[4];
            #pragma unroll
            for (int rr = 0; rr < 4; rr++) {
                float xv = sX[(rg * 4 + rr) * XP_XSTRIDE + d];
                asm("mov.b64 %0, {%1, %1};" : "=l"(x2[rr]) : "f"(xv));
            }
            const uint32_t wrow = smem_u32(sW + d * XP_WSTRIDE + 2 * cq);
            #pragma unroll
            for (int qq = 0; qq < 8; qq++) {
                unsigned long long w2;
                asm volatile("ld.shared.u64 %0, [%1];"
                             : "=l"(w2) : "r"(wrow + qq * 64));
                #pragma unroll
                for (int rr = 0; rr < 4; rr++)
                    asm volatile("fma.rn.f32x2 %0, %1, %2, %0;"
                                 : "+l"(acc[rr][qq]) : "l"(x2[rr]), "l"(w2));
            }
        }

        #pragma unroll
        for (int rr = 0; rr < 4; rr++) {
            int r = rg * 4 + rr;
            int tt = r >> 3, bb = r & 7;
            int t = tblk * 16 + tt;
            #pragma unroll
            for (int qq = 0; qq < 8; qq++) {
                int cglob = cp0 + 2 * (cq + 8 * qq);
                int gate = cglob >> 8, rem = cglob & 255;
                int cg = rem >> 4, lj = rem & 15;
                float lo, hi;
                asm("mov.b64 {%0,%1}, %2;" : "=f"(lo), "=f"(hi) : "l"(acc[rr][qq]));
                float2* dst = reinterpret_cast<float2*>(
                    g_xp + ((size_t)((t * 16 + cg) * 8 + bg)) * 512
                         + bb * 64 + gate * 16 + lj);
                *dst = make_float2(lo, hi);
            }
        }
    }

    // publish tblk progress (release pairs with scan's acquire)
    __syncthreads();
    if (tid == 0)
        asm volatile("red.release.gpu.global.add.u32 [%0], %1;"
                     :: "l"(&xp_cnt[tblk * 32]), "r"(1u) : "memory");
}

// ===========================================================================
// scan body (R16 verbatim + xp_cnt gating)
// ===========================================================================
__device__ void scan_body(const float* __restrict__ W_h) {
    extern __shared__ float smem[];
    float* sW2   = smem + SM_SW2;
    float* sH    = smem + SM_H;
    float* sPart = smem + SM_PART;
    float* sC    = smem + SM_C;

    const int tid = threadIdx.x;
    const int cg  = blockIdx.x & 15;
    const int bg  = blockIdx.x >> 4;
    const int j0  = cg * JPC;

    for (int idx = tid; idx < KC * 8 * NCOL; idx += NTHREADS) {
        int k = idx >> 6, c = idx & 63;
        int gate = c >> 4, lj = c & 15;
        sW2[k * SWSTR + c] = W_h[(size_t)k * G4H + gate * HID + j0 + lj];
    }
    if (tid < JPC * BPC) sC[tid] = 0.0f;
    __syncthreads();

    const int w    = tid >> 5;
    const int lane = tid & 31;
    const int hw   = lane >> 4;
    const int lc   = lane & 15;
    const int k0   = w * KC;
    const int c0   = 4 * lc;

    unsigned long long wreg[2][KC];
    {
        const uint32_t wb = smem_u32(sW2 + k0 * SWSTR + c0);
        #pragma unroll
        for (int k = 0; k < KC; k++) {
            asm volatile("ld.shared.u64 %0, [%1];"
                         : "=l"(wreg[0][k]) : "r"(wb + k * (SWSTR * 4)));
            asm volatile("ld.shared.u64 %0, [%1];"
                         : "=l"(wreg[1][k]) : "r"(wb + k * (SWSTR * 4) + 8));
        }
    }
    __syncthreads();

    const uint32_t hbase  = smem_u32(sH + k0 * BPC + 4 * hw);
    const uint32_t hstore = smem_u32(sH + k0 * BPC) + lane * 16;

    const int lj = tid >> 3;
    const int bb = tid & 7;

    for (int s = 0; s < TSTEPS; s++) {
        const int rbuf = s & 1;
        float* sP = sPart + rbuf * (8 * BPC * PSTR);

        // ---- gate on xproj progress (once per 16 steps; epi warps only)
        if ((s & 15) == 0 && tid < JPC * BPC) {
            if ((tid & 31) == 0) {
                const unsigned* cp = &xp_cnt[(s >> 4) * 32];
                unsigned v;
                for (;;) {
                    asm volatile("ld.acquire.gpu.global.u32 %0, [%1];"
                                 : "=r"(v) : "l"(cp) : "memory");
                    if (v >= 8u) break;
                    __nanosleep(128);
                }
            }
            __syncwarp();
        }

        // ---- prefetch x_proj gate inputs for epilogue (tid<128)
        float xr[4];
        if (tid < JPC * BPC) {
            const float* xpb = g_xp + ((size_t)((s * 16 + cg) * 8 + bg)) * 512
                             + bb * 64 + lj;
            #pragma unroll
            for (int gate = 0; gate < 4; gate++)
                xr[gate] = __ldcg(xpb + gate * 16);
        }

        // ---- arrival-order poll + split GEMM on the two producer blocks
        const unsigned long long* pA = &g_hx[rbuf][bg][2 * w][4 * lane];
        const unsigned long long* pB = &g_hx[rbuf][bg][2 * w + 1][4 * lane];
        unsigned long long va[4], vb[4];
        const unsigned exp_tag = (unsigned)s;
        #pragma unroll
        for (int i = 0; i < 4; i++) { va[i] = ld_relaxed_u64(pA + i);
                                      vb[i] = ld_relaxed_u64(pB + i); }
        bool aReady, bReady;
        for (;;) {
            bool okA = true, okB = true;
            #pragma unroll
            for (int i = 0; i < 4; i++) {
                if ((unsigned)(va[i] >> 32) != exp_tag) okA = false;
                if ((unsigned)(vb[i] >> 32) != exp_tag) okB = false;
            }
            aReady = __all_sync(0xffffffffu, okA);
            bReady = __all_sync(0xffffffffu, okB);
            if (aReady || bReady) break;
            #pragma unroll
            for (int i = 0; i < 4; i++) {
                if ((unsigned)(va[i] >> 32) != exp_tag)
                    va[i] = ld_relaxed_u64(pA + i);
                if ((unsigned)(vb[i] >> 32) != exp_tag)
                    vb[i] = ld_relaxed_u64(pB + i);
            }
        }

        unsigned long long acc[2][4];
        #pragma unroll
        for (int p = 0; p < 2; p++)
            #pragma unroll
            for (int i = 0; i < 4; i++) acc[p][i] = 0ull;

        if (aReady) {
            STAGE_BLOCK(va, 0);
            __syncwarp();
            GEMM_HALF(0);
            if (!bReady) POLL_BLOCK(vb, pB);
            STAGE_BLOCK(vb, 512);
            __syncwarp();
            GEMM_HALF(16);
        } else {
            STAGE_BLOCK(vb, 512);
            __syncwarp();
            GEMM_HALF(16);
            POLL_BLOCK(va, pA);
            STAGE_BLOCK(va, 0);
            __syncwarp();
            GEMM_HALF(0);
        }

        // ---- write partials
        #pragma unroll
        for (int i = 0; i < 4; i++) {
            int row = (w * BPC + 4 * hw + i) * PSTR;
            *reinterpret_cast<unsigned long long*>(sP + row + c0)     = acc[0][i];
            *reinterpret_cast<unsigned long long*>(sP + row + c0 + 2) = acc[1][i];
        }
        __syncthreads();

        // ---- epilogue (warps 0-3): publish-early
        if (tid < JPC * BPC) {
            float g4[4];
            #pragma unroll
            for (int gate = 0; gate < 4; gate++) {
                int c = gate * JPC + lj;
                float v = xr[gate];
                #pragma unroll
                for (int q = 0; q < 8; q++)
                    v += sP[(q * BPC + bb) * PSTR + c];
                g4[gate] = v;
            }
            float e2 = __expf(-2.0f * g4[2]);
            float e0 = __expf(-g4[0]);
            float e1 = __expf(-g4[1]);
            float e3 = __expf(-g4[3]);
            float gg = __fdividef(2.0f, 1.0f + e2) - 1.0f;
            float ig = __fdividef(1.0f, 1.0f + e0);
            float fg = __fdividef(1.0f, 1.0f + e1);
            float cnew = fg * sC[tid] + ig * gg;
            float ech = __expf(-2.0f * cnew);
            float og = __fdividef(1.0f, 1.0f + e3);
            float hnew = og * (__fdividef(2.0f, 1.0f + ech) - 1.0f);

            unsigned long long pk;
            asm("mov.b64 %0, {%1, %2};"
                : "=l"(pk) : "r"(__float_as_uint(hnew)), "r"((unsigned)(s + 1)));
            asm volatile("st.relaxed.gpu.global.u64 [%0], %1;"
                         :: "l"(&g_hx[rbuf ^ 1][bg][cg][tid]), "l"(pk)
                         : "memory");
            sC[tid] = cnew;
        }
    }
}

// ===========================================================================
// fused kernel: bids 0-127 = scan; bids 128-147 = persistent xproj loop
// ===========================================================================
__global__ void __launch_bounds__(NTHREADS, 1)
fused_kernel(const float* __restrict__ x,
             const float* __restrict__ W_x,
             const float* __restrict__ W_h,
             const float* __restrict__ bias) {
    if (blockIdx.x < NCTA_SCAN) {
        scan_body(W_h);
    } else {
        const int r = blockIdx.x - NCTA_SCAN;
        for (int idx = r; idx < NTILES; idx += NCTA_XP)
            xproj_tile(x, W_x, bias, idx);
    }
}

// ---------------------------------------------------------------------------
// final FC: h_2048 (tag 2048) lives in g_hx[0][bg][k>>4][(k&15)*8+bb] low bits
// ---------------------------------------------------------------------------
__global__ void fc_kernel(const float* __restrict__ fc_w,
                          const float* __restrict__ fc_b,
                          float* __restrict__ out) {
    int b = blockIdx.x;
    int d = threadIdx.x;
    int bg = b >> 3, bb = b & 7;
    float acc = fc_b[d];
    #pragma unroll 8
    for (int k = 0; k < HID; k++) {
        unsigned long long v = g_hx[0][bg][k >> 4][(k & 15) * 8 + bb];
        acc += __uint_as_float((unsigned)v) * fc_w[k * DOUT + d];
    }
    out[b * DOUT + d] = acc;
}

// ---------------------------------------------------------------------------
extern "C" void kernel_launch(void* const* d_in, const int* in_sizes, int n_in,
                              void* d_out, int out_size) {
    const float* x    = (const float*)d_in[0];
    const float* W_x  = (const float*)d_in[1];
    const float* W_h  = (const float*)d_in[2];
    const float* bvec = (const float*)d_in[3];
    const float* fc_w = (const float*)d_in[4];
    const float* fc_b = (const float*)d_in[5];
    float* out = (float*)d_out;

    cudaFuncSetAttribute(fused_kernel,
                         cudaFuncAttributeMaxDynamicSharedMemorySize, XPK_BYTES);

    init_kernel<<<(2 * 8 * 16 * JPC * BPC + 255) / 256, 256>>>();
    fused_kernel<<<NCTA_TOTAL, NTHREADS, XPK_BYTES>>>(x, W_x, W_h, bvec);
    fc_kernel<<<BATCH, DOUT>>>(fc_w, fc_b, out);
}